// round 6
// baseline (speedup 1.0000x reference)
#include <cuda_runtime.h>

// db2 filter constants
#define DL0 (-0.12940952255092145f)
#define DL1 ( 0.22414386804185735f)
#define DL2 ( 0.836516303737469f)
#define DL3 ( 0.48296291314469025f)
#define DH0 (-0.48296291314469025f)
#define DH1 ( 0.836516303737469f)
#define DH2 (-0.22414386804185735f)
#define DH3 (-0.12940952255092145f)
#define RL0 ( 0.48296291314469025f)
#define RL1 ( 0.836516303737469f)
#define RL2 ( 0.22414386804185735f)
#define RL3 (-0.12940952255092145f)
#define RH0 (-0.12940952255092145f)
#define RH1 (-0.22414386804185735f)
#define RH2 ( 0.836516303737469f)
#define RH3 (-0.48296291314469025f)

static constexpr int D        = 512;
static constexpr int WARPS_PB = 8;     // one full row per warp
static constexpr int TPB      = WARPS_PB * 32;
static constexpr unsigned FULL = 0xffffffffu;

// 256-bit global load/store (sm_100+)
#define LDG256(r, p)                                                          \
    asm("ld.global.v8.f32 {%0,%1,%2,%3,%4,%5,%6,%7}, [%8];"                   \
        : "=f"((r)[0]), "=f"((r)[1]), "=f"((r)[2]), "=f"((r)[3]),             \
          "=f"((r)[4]), "=f"((r)[5]), "=f"((r)[6]), "=f"((r)[7])              \
        : "l"(p))

#define STG256(p, r)                                                          \
    asm volatile("st.global.v8.f32 [%0], {%1,%2,%3,%4,%5,%6,%7,%8};"          \
        :: "l"(p),                                                            \
           "f"((r)[0]), "f"((r)[1]), "f"((r)[2]), "f"((r)[3]),                \
           "f"((r)[4]), "f"((r)[5]), "f"((r)[6]), "f"((r)[7])                 \
        : "memory")

// 8 outputs from stencil window s[0..11] = x[c-2 .. c+9] and weights w[0..4].
__device__ __forceinline__ void oct_compute(const float* __restrict__ s,
                                            const float* __restrict__ w,
                                            float* __restrict__ z)
{
    float cA[5], cD[5];
#pragma unroll
    for (int i = 0; i < 5; i++) {
        cA[i] = fmaf(s[2*i], DL3, fmaf(s[2*i+1], DL2, fmaf(s[2*i+2], DL1, s[2*i+3] * DL0)));
        cD[i] = fmaf(s[2*i], DH3, fmaf(s[2*i+1], DH2, fmaf(s[2*i+2], DH1, s[2*i+3] * DH0)));
        cD[i] *= w[i];
    }
#pragma unroll
    for (int i = 0; i < 4; i++) {
        float ze = fmaf(RL2, cA[i], fmaf(RL0, cA[i+1], fmaf(RH2, cD[i], RH0 * cD[i+1])));
        float zo = fmaf(RL3, cA[i], fmaf(RL1, cA[i+1], fmaf(RH3, cD[i], RH1 * cD[i+1])));
        z[2*i]   = ze > 0.0f ? ze : 0.01f * ze;
        z[2*i+1] = zo > 0.0f ? zo : 0.01f * zo;
    }
}

// One warp per 512-float row, two warp-contiguous 256-float chunks:
//   oct A: x[8*lane .. 8*lane+7]        (chunk 0..255)
//   oct B: x[256 + 8*lane .. +7]        (chunk 256..511)
// Each LDG.256/STG.256 instruction covers a contiguous 1024B span.
// All halo via 8 shuffles/warp (select + circular shuffle folds the A<->B
// seam in); row boundaries are register fixups (symmetric extension).
__global__ __launch_bounds__(TPB)
void wavelet_db2_v8_kernel(const float* __restrict__ x,
                           const float* __restrict__ weight,
                           float* __restrict__ out)
{
    const int warp = threadIdx.x >> 5;
    const int lane = threadIdx.x & 31;

    const long long row = (long long)blockIdx.x * WARPS_PB + warp;
    const float* __restrict__ rowp = x + row * D;

    float a[8], b[8];
    LDG256(a, rowp + (lane << 3));          // x[8L .. 8L+7]
    LDG256(b, rowp + 256 + (lane << 3));    // x[256+8L .. +7]

    const int up = (lane + 31) & 31;        // circular lane-1
    const int dn = (lane + 1) & 31;         // circular lane+1

    // ---- oct A halo ----
    float am2 = __shfl_up_sync(FULL, a[6], 1);      // x[8L-2]
    float am1 = __shfl_up_sync(FULL, a[7], 1);      // x[8L-1]
    if (lane == 0) { am2 = a[1]; am1 = a[0]; }      // symmetric left: x[1], x[0]
    // x[8L+8], x[8L+9]: lane+1's a0/a1, except lane31 -> lane0's b0/b1 (seam)
    const float uA0 = (lane == 0) ? b[0] : a[0];
    const float uA1 = (lane == 0) ? b[1] : a[1];
    const float ap8 = __shfl_sync(FULL, uA0, dn);
    const float ap9 = __shfl_sync(FULL, uA1, dn);

    // ---- oct B halo ----
    // x[256+8L-2], x[256+8L-1]: lane-1's b6/b7, except lane0 -> lane31's a6/a7
    const float uB6 = (lane == 31) ? a[6] : b[6];
    const float uB7 = (lane == 31) ? a[7] : b[7];
    const float bm2 = __shfl_sync(FULL, uB6, up);
    const float bm1 = __shfl_sync(FULL, uB7, up);
    float bp8 = __shfl_down_sync(FULL, b[0], 1);    // x[256+8L+8]
    float bp9 = __shfl_down_sync(FULL, b[1], 1);    // x[256+8L+9]
    if (lane == 31) { bp8 = b[7]; bp9 = b[6]; }     // symmetric right: x[511], x[510]

    // ---- weights: oct A -> w[4L .. 4L+4], oct B -> w[128+4L .. +4] ----
    const int kA = lane << 2;
    const float4 w4A = __ldg(reinterpret_cast<const float4*>(weight + kA));
    const float  wsA = __ldg(weight + kA + 4);
    const float4 w4B = __ldg(reinterpret_cast<const float4*>(weight + 128 + kA));
    const float  wsB = __ldg(weight + 132 + kA);
    const float wA[5] = {w4A.x, w4A.y, w4A.z, w4A.w, wsA};
    const float wB[5] = {w4B.x, w4B.y, w4B.z, w4B.w, wsB};

    // ---- compute + store ----
    float* op = out + row * D;

    const float sA[12] = {am2, am1, a[0], a[1], a[2], a[3], a[4], a[5], a[6], a[7], ap8, ap9};
    float zA[8];
    oct_compute(sA, wA, zA);
    STG256(op + (lane << 3), zA);

    const float sB[12] = {bm2, bm1, b[0], b[1], b[2], b[3], b[4], b[5], b[6], b[7], bp8, bp9};
    float zB[8];
    oct_compute(sB, wB, zB);
    STG256(op + 256 + (lane << 3), zB);
}

extern "C" void kernel_launch(void* const* d_in, const int* in_sizes, int n_in,
                              void* d_out, int out_size)
{
    const float* x = (const float*)d_in[0];   // (B, 512) fp32
    const float* w = (const float*)d_in[1];   // (2, 257) fp32
    float* out = (float*)d_out;               // (B, 512) fp32

    const int nrows = in_sizes[0] / D;        // 65536
    const int grid  = nrows / WARPS_PB;       // 8192

    wavelet_db2_v8_kernel<<<grid, TPB>>>(x, w, out);
}

// round 7
// speedup vs baseline: 1.0014x; 1.0014x over previous
#include <cuda_runtime.h>

// db2 filter constants
#define DL0 (-0.12940952255092145f)
#define DL1 ( 0.22414386804185735f)
#define DL2 ( 0.836516303737469f)
#define DL3 ( 0.48296291314469025f)
#define DH0 (-0.48296291314469025f)
#define DH1 ( 0.836516303737469f)
#define DH2 (-0.22414386804185735f)
#define DH3 (-0.12940952255092145f)
#define RL0 ( 0.48296291314469025f)
#define RL1 ( 0.836516303737469f)
#define RL2 ( 0.22414386804185735f)
#define RL3 (-0.12940952255092145f)
#define RH0 (-0.12940952255092145f)
#define RH1 (-0.22414386804185735f)
#define RH2 ( 0.836516303737469f)
#define RH3 (-0.48296291314469025f)

static constexpr int D        = 512;
static constexpr int WARPS_PB = 8;     // two rows per warp
static constexpr int ROWS_PW  = 2;
static constexpr int TPB      = WARPS_PB * 32;
static constexpr unsigned FULL = 0xffffffffu;

// 256-bit streaming global load/store (sm_100+)
#define LDG256CS(r, p)                                                        \
    asm("ld.global.cs.v8.f32 {%0,%1,%2,%3,%4,%5,%6,%7}, [%8];"                \
        : "=f"((r)[0]), "=f"((r)[1]), "=f"((r)[2]), "=f"((r)[3]),             \
          "=f"((r)[4]), "=f"((r)[5]), "=f"((r)[6]), "=f"((r)[7])              \
        : "l"(p))

#define STG256CS(p, r)                                                        \
    asm volatile("st.global.cs.v8.f32 [%0], {%1,%2,%3,%4,%5,%6,%7,%8};"       \
        :: "l"(p),                                                            \
           "f"((r)[0]), "f"((r)[1]), "f"((r)[2]), "f"((r)[3]),                \
           "f"((r)[4]), "f"((r)[5]), "f"((r)[6]), "f"((r)[7])                 \
        : "memory")

// 8 outputs from stencil window s[0..11] = x[c-2 .. c+9] and weights w[0..4].
__device__ __forceinline__ void oct_compute(const float* __restrict__ s,
                                            const float* __restrict__ w,
                                            float* __restrict__ z)
{
    float cA[5], cD[5];
#pragma unroll
    for (int i = 0; i < 5; i++) {
        cA[i] = fmaf(s[2*i], DL3, fmaf(s[2*i+1], DL2, fmaf(s[2*i+2], DL1, s[2*i+3] * DL0)));
        cD[i] = fmaf(s[2*i], DH3, fmaf(s[2*i+1], DH2, fmaf(s[2*i+2], DH1, s[2*i+3] * DH0)));
        cD[i] *= w[i];
    }
#pragma unroll
    for (int i = 0; i < 4; i++) {
        float ze = fmaf(RL2, cA[i], fmaf(RL0, cA[i+1], fmaf(RH2, cD[i], RH0 * cD[i+1])));
        float zo = fmaf(RL3, cA[i], fmaf(RL1, cA[i+1], fmaf(RH3, cD[i], RH1 * cD[i+1])));
        z[2*i]   = ze > 0.0f ? ze : 0.01f * ze;
        z[2*i+1] = zo > 0.0f ? zo : 0.01f * zo;
    }
}

// Halo (8 shuffles, uniform flow) + compute + two STG.256 for one row held as
// oct A = x[8L..8L+7], oct B = x[256+8L..+7].
__device__ __forceinline__ void row_process(const float* __restrict__ a,
                                            const float* __restrict__ b,
                                            int lane,
                                            const float* __restrict__ wA,
                                            const float* __restrict__ wB,
                                            float* __restrict__ op)
{
    const int up = (lane + 31) & 31;
    const int dn = (lane + 1) & 31;

    // oct A halo
    float am2 = __shfl_up_sync(FULL, a[6], 1);      // x[8L-2]
    float am1 = __shfl_up_sync(FULL, a[7], 1);      // x[8L-1]
    if (lane == 0) { am2 = a[1]; am1 = a[0]; }      // symmetric left: x[1], x[0]
    const float uA0 = (lane == 0) ? b[0] : a[0];
    const float uA1 = (lane == 0) ? b[1] : a[1];
    const float ap8 = __shfl_sync(FULL, uA0, dn);   // x[8L+8]
    const float ap9 = __shfl_sync(FULL, uA1, dn);   // x[8L+9]

    // oct B halo
    const float uB6 = (lane == 31) ? a[6] : b[6];
    const float uB7 = (lane == 31) ? a[7] : b[7];
    const float bm2 = __shfl_sync(FULL, uB6, up);   // x[256+8L-2]
    const float bm1 = __shfl_sync(FULL, uB7, up);   // x[256+8L-1]
    float bp8 = __shfl_down_sync(FULL, b[0], 1);    // x[256+8L+8]
    float bp9 = __shfl_down_sync(FULL, b[1], 1);    // x[256+8L+9]
    if (lane == 31) { bp8 = b[7]; bp9 = b[6]; }     // symmetric right: x[511], x[510]

    const float sA[12] = {am2, am1, a[0], a[1], a[2], a[3], a[4], a[5], a[6], a[7], ap8, ap9};
    float zA[8];
    oct_compute(sA, wA, zA);
    STG256CS(op + (lane << 3), zA);

    const float sB[12] = {bm2, bm1, b[0], b[1], b[2], b[3], b[4], b[5], b[6], b[7], bp8, bp9};
    float zB[8];
    oct_compute(sB, wB, zB);
    STG256CS(op + 256 + (lane << 3), zB);
}

// One warp per TWO rows; all 4 LDG.256 front-batched (MLP_p1 = 4).
__global__ __launch_bounds__(TPB)
void wavelet_db2_v8x2_kernel(const float* __restrict__ x,
                             const float* __restrict__ weight,
                             float* __restrict__ out)
{
    const int warp = threadIdx.x >> 5;
    const int lane = threadIdx.x & 31;

    const long long pair = (long long)blockIdx.x * WARPS_PB + warp;
    const long long r0   = pair * ROWS_PW;

    const float* __restrict__ p0 = x + r0 * D;
    const float* __restrict__ p1 = p0 + D;
    const int co = lane << 3;

    // ---- front-batched loads: 4x LDG.256 back-to-back ----
    float a0[8], b0[8], a1[8], b1[8];
    LDG256CS(a0, p0 + co);
    LDG256CS(b0, p0 + 256 + co);
    LDG256CS(a1, p1 + co);
    LDG256CS(b1, p1 + 256 + co);

    // ---- weights, loaded once, shared by both rows ----
    const int kA = lane << 2;
    const float4 w4A = __ldg(reinterpret_cast<const float4*>(weight + kA));
    const float  wsA = __ldg(weight + kA + 4);
    const float4 w4B = __ldg(reinterpret_cast<const float4*>(weight + 128 + kA));
    const float  wsB = __ldg(weight + 132 + kA);
    const float wA[5] = {w4A.x, w4A.y, w4A.z, w4A.w, wsA};
    const float wB[5] = {w4B.x, w4B.y, w4B.z, w4B.w, wsB};

    float* o0 = out + r0 * D;
    row_process(a0, b0, lane, wA, wB, o0);
    row_process(a1, b1, lane, wA, wB, o0 + D);
}

extern "C" void kernel_launch(void* const* d_in, const int* in_sizes, int n_in,
                              void* d_out, int out_size)
{
    const float* x = (const float*)d_in[0];   // (B, 512) fp32
    const float* w = (const float*)d_in[1];   // (2, 257) fp32
    float* out = (float*)d_out;               // (B, 512) fp32

    const int nrows = in_sizes[0] / D;                    // 65536
    const int grid  = nrows / (WARPS_PB * ROWS_PW);       // 4096

    wavelet_db2_v8x2_kernel<<<grid, TPB>>>(x, w, out);
}

// round 8
// speedup vs baseline: 1.0383x; 1.0368x over previous
#include <cuda_runtime.h>

// db2 filter constants
#define DL0 (-0.12940952255092145f)
#define DL1 ( 0.22414386804185735f)
#define DL2 ( 0.836516303737469f)
#define DL3 ( 0.48296291314469025f)
#define DH0 (-0.48296291314469025f)
#define DH1 ( 0.836516303737469f)
#define DH2 (-0.22414386804185735f)
#define DH3 (-0.12940952255092145f)
#define RL0 ( 0.48296291314469025f)
#define RL1 ( 0.836516303737469f)
#define RL2 ( 0.22414386804185735f)
#define RL3 (-0.12940952255092145f)
#define RH0 (-0.12940952255092145f)
#define RH1 (-0.22414386804185735f)
#define RH2 ( 0.836516303737469f)
#define RH3 (-0.48296291314469025f)

static constexpr int D        = 512;
static constexpr int WARPS_PB = 8;     // one full row per warp
static constexpr int TPB      = WARPS_PB * 32;
static constexpr unsigned FULL = 0xffffffffu;

// 4 outputs from quad v = x[c..c+3] with halo (m2,m1 | p4,p5) and weights.
__device__ __forceinline__ float4 quad_compute(float m2, float m1, float4 v,
                                               float p4, float p5,
                                               float w0, float w1, float w2)
{
    const float cA0 = fmaf(m2,  DL3, fmaf(m1,  DL2, fmaf(v.x, DL1, v.y * DL0)));
    const float cA1 = fmaf(v.x, DL3, fmaf(v.y, DL2, fmaf(v.z, DL1, v.w * DL0)));
    const float cA2 = fmaf(v.z, DL3, fmaf(v.w, DL2, fmaf(p4,  DL1, p5  * DL0)));

    float cD0 = fmaf(m2,  DH3, fmaf(m1,  DH2, fmaf(v.x, DH1, v.y * DH0)));
    float cD1 = fmaf(v.x, DH3, fmaf(v.y, DH2, fmaf(v.z, DH1, v.w * DH0)));
    float cD2 = fmaf(v.z, DH3, fmaf(v.w, DH2, fmaf(p4,  DH1, p5  * DH0)));
    cD0 *= w0; cD1 *= w1; cD2 *= w2;

    float4 z;
    z.x = fmaf(RL2, cA0, fmaf(RL0, cA1, fmaf(RH2, cD0, RH0 * cD1)));
    z.y = fmaf(RL3, cA0, fmaf(RL1, cA1, fmaf(RH3, cD0, RH1 * cD1)));
    z.z = fmaf(RL2, cA1, fmaf(RL0, cA2, fmaf(RH2, cD1, RH0 * cD2)));
    z.w = fmaf(RL3, cA1, fmaf(RL1, cA2, fmaf(RH3, cD1, RH1 * cD2)));
    z.x = z.x > 0.0f ? z.x : 0.01f * z.x;
    z.y = z.y > 0.0f ? z.y : 0.01f * z.y;
    z.z = z.z > 0.0f ? z.z : 0.01f * z.z;
    z.w = z.w > 0.0f ? z.w : 0.01f * z.w;
    return z;
}

// One warp per 512-float row, owned as FOUR warp-contiguous float4 quads:
//   quad q: x[128q + 4*lane .. +3]   (q = 0..3)
// Every LDG.128/STG.128 instruction covers a contiguous 512B span; all 4
// loads front-batched (MLP_p1=4). All chunk seams are warp-internal: handled
// by select + circular shuffle (uniform control flow, zero halo __ldg).
// Row edges are register fixups (symmetric extension).
__global__ __launch_bounds__(TPB, 6)
void wavelet_db2_q4_kernel(const float* __restrict__ x,
                           const float* __restrict__ weight,
                           float* __restrict__ out)
{
    const int warp = threadIdx.x >> 5;
    const int lane = threadIdx.x & 31;

    const long long row = (long long)blockIdx.x * WARPS_PB + warp;
    const float* __restrict__ rowp = x + row * D;
    const int co = lane << 2;

    // ---- front-batched, perfectly-coalesced loads ----
    float4 v[4];
#pragma unroll
    for (int q = 0; q < 4; q++)
        v[q] = __ldcs(reinterpret_cast<const float4*>(rowp + (q << 7) + co));

    const int up = (lane + 31) & 31;   // circular lane-1 (lane0 <- lane31)
    const int dn = (lane + 1) & 31;    // circular lane+1 (lane31 <- lane0)

    float* op = out + row * D;

#pragma unroll
    for (int q = 0; q < 4; q++) {
        // left halo: x[cq-2], x[cq-1] from lane-1's v[q].zw;
        // lane0 gets lane31's v[q-1].zw via the circular shuffle (seam),
        // except q=0 where it's the symmetric extension.
        const float uz = (q > 0 && lane == 31) ? v[q-1].z : v[q].z;
        const float uw = (q > 0 && lane == 31) ? v[q-1].w : v[q].w;
        float m2 = __shfl_sync(FULL, uz, up);
        float m1 = __shfl_sync(FULL, uw, up);
        if (q == 0 && lane == 0) { m2 = v[0].y; m1 = v[0].x; }   // x[1], x[0]

        // right halo: x[cq+4], x[cq+5] from lane+1's v[q].xy;
        // lane31 gets lane0's v[q+1].xy via the circular shuffle (seam),
        // except q=3 where it's the symmetric extension.
        const float ux = (q < 3 && lane == 0) ? v[q+1].x : v[q].x;
        const float uy = (q < 3 && lane == 0) ? v[q+1].y : v[q].y;
        float p4 = __shfl_sync(FULL, ux, dn);
        float p5 = __shfl_sync(FULL, uy, dn);
        if (q == 3 && lane == 31) { p4 = v[3].w; p5 = v[3].z; }  // x[511], x[510]

        // weights: w[k..k+2], k = 64q + 2*lane (even -> aligned float2)
        const int k = (q << 6) + (lane << 1);
        const float2 w01 = __ldg(reinterpret_cast<const float2*>(weight) + (k >> 1));
        const float  w2  = __ldg(weight + k + 2);

        const float4 z = quad_compute(m2, m1, v[q], p4, p5, w01.x, w01.y, w2);
        __stcs(reinterpret_cast<float4*>(op + (q << 7) + co), z);
    }
}

extern "C" void kernel_launch(void* const* d_in, const int* in_sizes, int n_in,
                              void* d_out, int out_size)
{
    const float* x = (const float*)d_in[0];   // (B, 512) fp32
    const float* w = (const float*)d_in[1];   // (2, 257) fp32
    float* out = (float*)d_out;               // (B, 512) fp32

    const int nrows = in_sizes[0] / D;        // 65536
    const int grid  = nrows / WARPS_PB;       // 8192

    wavelet_db2_q4_kernel<<<grid, TPB>>>(x, w, out);
}